// round 16
// baseline (speedup 1.0000x reference)
#include <cuda_runtime.h>
#include <cuda_bf16.h>

// ---------------------------------------------------------------------------
// ZBL screened-Coulomb pair energy with switching polynomial, scatter to atoms
//
// Inputs (metadata order):
//   0: rij             float32 [E]
//   1: covalent_radii  float32 [4]
//   2: atomic_numbers  float32 [4]
//   3: first_atom      int32   [E]
//   4: second_atom     int32   [E]
//   5: atom_type_index int32   [N]
// Output: float32 [N]
// ---------------------------------------------------------------------------

#define MAX_PACK_WORDS 16384   // up to 262144 atoms at 2 bits/atom

__device__ unsigned int g_packed[MAX_PACK_WORDS];

// ---- fused setup: zero out (float4) + pack types (int4 x4 per word) -------
__global__ void zbl_setup(const int* __restrict__ type,
                          float* __restrict__ out, int n_atoms) {
    int t = blockIdx.x * blockDim.x + threadIdx.x;

    int nz4 = n_atoms >> 2;
    if (t < nz4) ((float4*)out)[t] = make_float4(0.f, 0.f, 0.f, 0.f);
    if (t == 0) for (int k = nz4 << 2; k < n_atoms; k++) out[k] = 0.0f;

    int nw   = (n_atoms + 15) >> 4;
    int full = n_atoms >> 4;
    if (t < full) {
        const int4* t4 = (const int4*)(type + (t << 4));
        int4 a = t4[0], b = t4[1], c = t4[2], d = t4[3];
        unsigned v =
              ((unsigned)a.x & 3u)        | (((unsigned)a.y & 3u) << 2)
            | (((unsigned)a.z & 3u) << 4) | (((unsigned)a.w & 3u) << 6)
            | (((unsigned)b.x & 3u) << 8) | (((unsigned)b.y & 3u) << 10)
            | (((unsigned)b.z & 3u) << 12)| (((unsigned)b.w & 3u) << 14)
            | (((unsigned)c.x & 3u) << 16)| (((unsigned)c.y & 3u) << 18)
            | (((unsigned)c.z & 3u) << 20)| (((unsigned)c.w & 3u) << 22)
            | (((unsigned)d.x & 3u) << 24)| (((unsigned)d.y & 3u) << 26)
            | (((unsigned)d.z & 3u) << 28)| (((unsigned)d.w & 3u) << 30);
        g_packed[t] = v;
    } else if (t < nw) {
        unsigned v = 0;
        int base = t << 4;
        int lim  = n_atoms - base;
        for (int k = 0; k < lim; k++)
            v |= ((unsigned)type[base + k] & 3u) << (2 * k);
        g_packed[t] = v;
    }
}

// ---- per-edge math --------------------------------------------------------
// tabA[p] = (rc, inv_a, halfFactor, A/6)   tabB[p] = (B/8, C/2)
__device__ __forceinline__ void zbl_edge(float r, int i,
                                         unsigned wi, unsigned wj, int j,
                                         const float4* __restrict__ tabA,
                                         const float2* __restrict__ tabB,
                                         float* __restrict__ out) {
    int ti = (wi >> ((i & 15) * 2)) & 3;
    int tj = (wj >> ((j & 15) * 2)) & 3;
    int p  = (ti << 2) | tj;
    float4 a4 = tabA[p];
    if (r <= a4.x) {
        float2 b2 = tabB[p];
        float x = -r * a4.y;          // -r / a
        // d_k * log2(e): exp2f maps straight to MUFU.EX2
        float s = 0.02817f * exp2f(0.29088274f * x)
                + 0.28022f * exp2f(0.58126184f * x)
                + 0.50986f * exp2f(1.35944400f * x)
                + 0.18175f * exp2f(4.61651600f * x);
        float r3  = r * r * r;
        float val = a4.z * __fdividef(s, r) + r3 * (a4.w + b2.x * r) + b2.y;
        atomicAdd(out + i, val);
    }
}

__global__ __launch_bounds__(768, 2)
void zbl_edge_kernel(const float* __restrict__ rij,
                     const int*   __restrict__ fa,
                     const int*   __restrict__ sa,
                     const float* __restrict__ cr,
                     const float* __restrict__ Z,
                     float*       __restrict__ out,
                     int E, int n_atoms) {
    // dynamic smem (32-bit words): [0..64) tabA | [64..96) tabB | pack
    extern __shared__ unsigned shraw[];
    float4*   tabA    = (float4*)shraw;
    float2*   tabB    = (float2*)(shraw + 64);
    unsigned* sh_pack = shraw + 96;

    if (threadIdx.x < 16) {
        int p = threadIdx.x;
        int ti = p >> 2, tj = p & 3;
        const float c[4] = {0.02817f, 0.28022f, 0.50986f, 0.18175f};
        const float d[4] = {0.20162f, 0.4029f, 0.94229f, 3.1998f};
        float zi = Z[ti], zj = Z[tj];
        float a     = 0.4685f / (powf(zi, 0.23f) + powf(zj, 0.23f));
        float inv_a = 1.0f / a;
        float rc    = cr[ti] + cr[tj];
        float phi = 0.f, dphi = 0.f, d2phi = 0.f;
#pragma unroll
        for (int k = 0; k < 4; k++) {
            float da = d[k] * inv_a;
            float ex = expf(-rc * da);
            phi   += c[k] * ex;
            dphi  -= c[k] * da * ex;
            d2phi += c[k] * da * da * ex;
        }
        float factor = 14.399645478425668f * zi * zj;
        float irc  = 1.0f / rc;
        float ec   = factor * irc * phi;
        float dec  = factor * irc * (-phi * irc + dphi);
        float d2ec = factor * irc * (d2phi - 2.0f * irc * dphi
                                     + 2.0f * phi * irc * irc);
        float A = (-3.0f * dec + rc * d2ec) * irc * irc;
        float B = ( 2.0f * dec - rc * d2ec) * irc * irc * irc;
        float C = -ec + rc * dec * 0.5f - rc * rc * d2ec * (1.0f / 12.0f);
        tabA[p] = make_float4(rc, inv_a, 0.5f * factor, A * (1.0f / 6.0f));
        tabB[p] = make_float2(B * 0.125f, C * 0.5f);
    }

    // 2-bit type pack -> SMEM (coalesced copy)
    int nw = (n_atoms + 15) >> 4;
    for (int k = threadIdx.x; k < nw; k += blockDim.x)
        sh_pack[k] = g_packed[k];
    __syncthreads();

    int nvec = E >> 2;
    const float4* r4p = (const float4*)rij;
    const int4*   f4p = (const int4*)fa;
    const int4*   s4p = (const int4*)sa;

    for (int v = blockIdx.x * blockDim.x + threadIdx.x; v < nvec;
         v += gridDim.x * blockDim.x) {
        float4 r4 = __ldcs(r4p + v);
        int4   f4 = __ldcs(f4p + v);
        int4   s4 = __ldcs(s4p + v);

        unsigned wf0 = sh_pack[f4.x >> 4];
        unsigned wf1 = sh_pack[f4.y >> 4];
        unsigned wf2 = sh_pack[f4.z >> 4];
        unsigned wf3 = sh_pack[f4.w >> 4];
        unsigned ws0 = sh_pack[s4.x >> 4];
        unsigned ws1 = sh_pack[s4.y >> 4];
        unsigned ws2 = sh_pack[s4.z >> 4];
        unsigned ws3 = sh_pack[s4.w >> 4];

        zbl_edge(r4.x, f4.x, wf0, ws0, s4.x, tabA, tabB, out);
        zbl_edge(r4.y, f4.y, wf1, ws1, s4.y, tabA, tabB, out);
        zbl_edge(r4.z, f4.z, wf2, ws2, s4.z, tabA, tabB, out);
        zbl_edge(r4.w, f4.w, wf3, ws3, s4.w, tabA, tabB, out);
    }

    int tail = E & 3;
    if (blockIdx.x == 0 && (int)threadIdx.x < tail) {
        int e = (nvec << 2) + threadIdx.x;
        int i = fa[e], j = sa[e];
        zbl_edge(rij[e], i, sh_pack[i >> 4], sh_pack[j >> 4], j,
                 tabA, tabB, out);
    }
}

// ---------------------------------------------------------------------------
extern "C" void kernel_launch(void* const* d_in, const int* in_sizes, int n_in,
                              void* d_out, int out_size) {
    const float* rij = (const float*)d_in[0];
    const float* cr  = (const float*)d_in[1];
    const float* Z   = (const float*)d_in[2];
    const int*   fa  = (const int*)d_in[3];
    const int*   sa  = (const int*)d_in[4];
    const int*   ty  = (const int*)d_in[5];
    int E       = in_sizes[0];
    int n_atoms = out_size;
    float* out  = (float*)d_out;

    // One carveout config across the graph (avoid per-replay reconfig).
    cudaFuncSetAttribute(zbl_setup,
                         cudaFuncAttributePreferredSharedMemoryCarveout, 100);
    cudaFuncSetAttribute(zbl_edge_kernel,
                         cudaFuncAttributePreferredSharedMemoryCarveout, 100);

    int nthread = n_atoms >> 2;                // covers zero + pack work
    zbl_setup<<<(nthread + 1023) / 1024, 1024>>>(ty, out, n_atoms);

    int nw = (n_atoms + 15) >> 4;
    size_t shbytes = (96 + (size_t)nw) * sizeof(unsigned);
    cudaFuncSetAttribute(zbl_edge_kernel,
                         cudaFuncAttributeMaxDynamicSharedMemorySize,
                         (int)((shbytes + 1023) & ~1023ull));
    zbl_edge_kernel<<<296, 768, shbytes>>>(rij, fa, sa, cr, Z, out,
                                           E, n_atoms);
}

// round 17
// speedup vs baseline: 1.0662x; 1.0662x over previous
#include <cuda_runtime.h>
#include <cuda_bf16.h>

// ---------------------------------------------------------------------------
// ZBL screened-Coulomb pair energy with switching polynomial, scatter to atoms
//
// Inputs (metadata order):
//   0: rij             float32 [E]
//   1: covalent_radii  float32 [4]
//   2: atomic_numbers  float32 [4]
//   3: first_atom      int32   [E]
//   4: second_atom     int32   [E]
//   5: atom_type_index int32   [N]
// Output: float32 [N]
// ---------------------------------------------------------------------------

#define MAX_PACK_WORDS 16384   // up to 262144 atoms at 2 bits/atom

__device__ unsigned int g_packed[MAX_PACK_WORDS];

// ---- fused setup: zero out (float4) + pack types (int4 x4 per word) -------
__global__ void zbl_setup(const int* __restrict__ type,
                          float* __restrict__ out, int n_atoms) {
    int t = blockIdx.x * blockDim.x + threadIdx.x;

    int nz4 = n_atoms >> 2;
    if (t < nz4) ((float4*)out)[t] = make_float4(0.f, 0.f, 0.f, 0.f);
    if (t == 0) for (int k = nz4 << 2; k < n_atoms; k++) out[k] = 0.0f;

    int nw   = (n_atoms + 15) >> 4;
    int full = n_atoms >> 4;
    if (t < full) {
        const int4* t4 = (const int4*)(type + (t << 4));
        int4 a = t4[0], b = t4[1], c = t4[2], d = t4[3];
        unsigned v =
              ((unsigned)a.x & 3u)        | (((unsigned)a.y & 3u) << 2)
            | (((unsigned)a.z & 3u) << 4) | (((unsigned)a.w & 3u) << 6)
            | (((unsigned)b.x & 3u) << 8) | (((unsigned)b.y & 3u) << 10)
            | (((unsigned)b.z & 3u) << 12)| (((unsigned)b.w & 3u) << 14)
            | (((unsigned)c.x & 3u) << 16)| (((unsigned)c.y & 3u) << 18)
            | (((unsigned)c.z & 3u) << 20)| (((unsigned)c.w & 3u) << 22)
            | (((unsigned)d.x & 3u) << 24)| (((unsigned)d.y & 3u) << 26)
            | (((unsigned)d.z & 3u) << 28)| (((unsigned)d.w & 3u) << 30);
        g_packed[t] = v;
    } else if (t < nw) {
        unsigned v = 0;
        int base = t << 4;
        int lim  = n_atoms - base;
        for (int k = 0; k < lim; k++)
            v |= ((unsigned)type[base + k] & 3u) << (2 * k);
        g_packed[t] = v;
    }
}

// ---- per-edge math --------------------------------------------------------
// tabA[p] = (rc, inv_a, halfFactor, A/6)   tabB[p] = (B/8, C/2)
__device__ __forceinline__ void zbl_edge(float r, int i,
                                         unsigned wi, unsigned wj, int j,
                                         const float4* __restrict__ tabA,
                                         const float2* __restrict__ tabB,
                                         float* __restrict__ out) {
    int ti = (wi >> ((i & 15) * 2)) & 3;
    int tj = (wj >> ((j & 15) * 2)) & 3;
    int p  = (ti << 2) | tj;
    float4 a4 = tabA[p];
    if (r <= a4.x) {
        float2 b2 = tabB[p];
        float x = -r * a4.y;          // -r / a
        // d_k * log2(e): exp2f maps straight to MUFU.EX2
        float s = 0.02817f * exp2f(0.29088274f * x)
                + 0.28022f * exp2f(0.58126184f * x)
                + 0.50986f * exp2f(1.35944400f * x)
                + 0.18175f * exp2f(4.61651600f * x);
        float r3  = r * r * r;
        float val = a4.z * __fdividef(s, r) + r3 * (a4.w + b2.x * r) + b2.y;
        atomicAdd(out + i, val);
    }
}

__global__ __launch_bounds__(1024, 1)
void zbl_edge_kernel(const float* __restrict__ rij,
                     const int*   __restrict__ fa,
                     const int*   __restrict__ sa,
                     const float* __restrict__ cr,
                     const float* __restrict__ Z,
                     float*       __restrict__ out,
                     int E, int n_atoms) {
    // dynamic smem (32-bit words): [0..64) tabA | [64..96) tabB | pack
    extern __shared__ unsigned shraw[];
    float4*   tabA    = (float4*)shraw;
    float2*   tabB    = (float2*)(shraw + 64);
    unsigned* sh_pack = shraw + 96;

    if (threadIdx.x < 16) {
        int p = threadIdx.x;
        int ti = p >> 2, tj = p & 3;
        const float c[4] = {0.02817f, 0.28022f, 0.50986f, 0.18175f};
        const float d[4] = {0.20162f, 0.4029f, 0.94229f, 3.1998f};
        float zi = Z[ti], zj = Z[tj];
        float a     = 0.4685f / (powf(zi, 0.23f) + powf(zj, 0.23f));
        float inv_a = 1.0f / a;
        float rc    = cr[ti] + cr[tj];
        float phi = 0.f, dphi = 0.f, d2phi = 0.f;
#pragma unroll
        for (int k = 0; k < 4; k++) {
            float da = d[k] * inv_a;
            float ex = expf(-rc * da);
            phi   += c[k] * ex;
            dphi  -= c[k] * da * ex;
            d2phi += c[k] * da * da * ex;
        }
        float factor = 14.399645478425668f * zi * zj;
        float irc  = 1.0f / rc;
        float ec   = factor * irc * phi;
        float dec  = factor * irc * (-phi * irc + dphi);
        float d2ec = factor * irc * (d2phi - 2.0f * irc * dphi
                                     + 2.0f * phi * irc * irc);
        float A = (-3.0f * dec + rc * d2ec) * irc * irc;
        float B = ( 2.0f * dec - rc * d2ec) * irc * irc * irc;
        float C = -ec + rc * dec * 0.5f - rc * rc * d2ec * (1.0f / 12.0f);
        tabA[p] = make_float4(rc, inv_a, 0.5f * factor, A * (1.0f / 6.0f));
        tabB[p] = make_float2(B * 0.125f, C * 0.5f);
    }

    // 2-bit type pack -> SMEM (coalesced copy)
    int nw = (n_atoms + 15) >> 4;
    for (int k = threadIdx.x; k < nw; k += blockDim.x)
        sh_pack[k] = g_packed[k];
    __syncthreads();

    int nvec   = E >> 2;
    int stride = gridDim.x * blockDim.x;
    const float4* r4p = (const float4*)rij;
    const int4*   f4p = (const int4*)fa;
    const int4*   s4p = (const int4*)sa;

    int v = blockIdx.x * blockDim.x + threadIdx.x;
    if (v < nvec) {
        // software pipeline: loads for iteration v+stride are issued before
        // the body of iteration v, so the DRAM latency is covered by a full
        // body's worth of independent work instead of being exposed.
        float4 r4 = __ldcs(r4p + v);
        int4   f4 = __ldcs(f4p + v);
        int4   s4 = __ldcs(s4p + v);
        for (;;) {
            int vn = v + stride;
            bool more = vn < nvec;
            float4 r4n;
            int4   f4n, s4n;
            if (more) {
                r4n = __ldcs(r4p + vn);
                f4n = __ldcs(f4p + vn);
                s4n = __ldcs(s4p + vn);
            }

            unsigned wf0 = sh_pack[f4.x >> 4];
            unsigned wf1 = sh_pack[f4.y >> 4];
            unsigned wf2 = sh_pack[f4.z >> 4];
            unsigned wf3 = sh_pack[f4.w >> 4];
            unsigned ws0 = sh_pack[s4.x >> 4];
            unsigned ws1 = sh_pack[s4.y >> 4];
            unsigned ws2 = sh_pack[s4.z >> 4];
            unsigned ws3 = sh_pack[s4.w >> 4];

            zbl_edge(r4.x, f4.x, wf0, ws0, s4.x, tabA, tabB, out);
            zbl_edge(r4.y, f4.y, wf1, ws1, s4.y, tabA, tabB, out);
            zbl_edge(r4.z, f4.z, wf2, ws2, s4.z, tabA, tabB, out);
            zbl_edge(r4.w, f4.w, wf3, ws3, s4.w, tabA, tabB, out);

            if (!more) break;
            v = vn;
            r4 = r4n; f4 = f4n; s4 = s4n;
        }
    }

    int tail = E & 3;
    if (blockIdx.x == 0 && (int)threadIdx.x < tail) {
        int e = (nvec << 2) + threadIdx.x;
        int i = fa[e], j = sa[e];
        zbl_edge(rij[e], i, sh_pack[i >> 4], sh_pack[j >> 4], j,
                 tabA, tabB, out);
    }
}

// ---------------------------------------------------------------------------
extern "C" void kernel_launch(void* const* d_in, const int* in_sizes, int n_in,
                              void* d_out, int out_size) {
    const float* rij = (const float*)d_in[0];
    const float* cr  = (const float*)d_in[1];
    const float* Z   = (const float*)d_in[2];
    const int*   fa  = (const int*)d_in[3];
    const int*   sa  = (const int*)d_in[4];
    const int*   ty  = (const int*)d_in[5];
    int E       = in_sizes[0];
    int n_atoms = out_size;
    float* out  = (float*)d_out;

    // One carveout config across the graph (avoid per-replay reconfig).
    cudaFuncSetAttribute(zbl_setup,
                         cudaFuncAttributePreferredSharedMemoryCarveout, 100);
    cudaFuncSetAttribute(zbl_edge_kernel,
                         cudaFuncAttributePreferredSharedMemoryCarveout, 100);

    int nthread = n_atoms >> 2;                // covers zero + pack work
    zbl_setup<<<(nthread + 1023) / 1024, 1024>>>(ty, out, n_atoms);

    int nw = (n_atoms + 15) >> 4;
    size_t shbytes = (96 + (size_t)nw) * sizeof(unsigned);
    cudaFuncSetAttribute(zbl_edge_kernel,
                         cudaFuncAttributeMaxDynamicSharedMemorySize,
                         (int)((shbytes + 1023) & ~1023ull));
    zbl_edge_kernel<<<296, 1024, shbytes>>>(rij, fa, sa, cr, Z, out,
                                            E, n_atoms);
}